// round 1
// baseline (speedup 1.0000x reference)
#include <cuda_runtime.h>

#define NN 86016
#define NE 4194304
#define H 32
#define NG 1024
#define NPG 84
#define ETOT (NE + NN)
#define BIG_NEG -1e30f

// ---------------- device scratch (no allocations allowed) ----------------
__device__ int    d_deg[NN];
__device__ float2 d_easum[NN];
__device__ int    d_cur[NN];
__device__ int    d_rowptr[NN + 1];
__device__ int    d_csrc[ETOT];
__device__ float2 d_cea[ETOT];
__device__ float  d_hA[NN * H];
__device__ float  d_hB[NN * H];
__device__ float  d_asrc[NN];
__device__ float  d_adst[NN];
__device__ float2 d_ce[4];
__device__ float  d_c0[2];

// ---------------- init ----------------
__global__ void k_init() {
    int i = blockIdx.x * blockDim.x + threadIdx.x;
    if (i < NN) { d_deg[i] = 0; d_easum[i] = make_float2(0.f, 0.f); }
}

// per-layer folded constants: ce[l] = We[l] @ att_edge[l]; c0 = (W0.a_s, W0.a_d)
__global__ void k_consts(const float* __restrict__ W0, const float* __restrict__ a_s,
                         const float* __restrict__ a_d, const float* __restrict__ We,
                         const float* __restrict__ a_e) {
    int w = threadIdx.x >> 5, lane = threadIdx.x & 31;
    if (w < 4) {
        float ae = a_e[w * 32 + lane];
        float p0 = We[w * 64 + lane] * ae;
        float p1 = We[w * 64 + 32 + lane] * ae;
        #pragma unroll
        for (int o = 16; o; o >>= 1) {
            p0 += __shfl_xor_sync(~0u, p0, o);
            p1 += __shfl_xor_sync(~0u, p1, o);
        }
        if (lane == 0) d_ce[w] = make_float2(p0, p1);
    } else {
        float w0 = W0[lane];
        float ps = w0 * a_s[lane];
        float pd = w0 * a_d[lane];
        #pragma unroll
        for (int o = 16; o; o >>= 1) {
            ps += __shfl_xor_sync(~0u, ps, o);
            pd += __shfl_xor_sync(~0u, pd, o);
        }
        if (lane == 0) { d_c0[0] = ps; d_c0[1] = pd; }
    }
}

// ---------------- CSR build ----------------
__global__ void k_hist(const int* __restrict__ ei, const float2* __restrict__ ea) {
    int e = blockIdx.x * blockDim.x + threadIdx.x;
    if (e >= NE) return;
    int d = ei[NE + e];
    atomicAdd(&d_deg[d], 1);
    float2 a = ea[e];
    atomicAdd(&d_easum[d].x, a.x);
    atomicAdd(&d_easum[d].y, a.y);
}

// single block, 1024 threads; N = 1024 * 84 exactly.
// builds rowptr (row size = deg+1 for self-loop), writes self-loop entries
// (src=n, ea = mean incoming edge_attr) into the first slot of each row,
// and initializes the scatter cursor to slot+1.
__global__ void k_scan() {
    __shared__ int sm[1024];
    int t = threadIdx.x;
    int base = t * NPG;
    int tot = 0;
    #pragma unroll 4
    for (int i = 0; i < NPG; i++) tot += d_deg[base + i] + 1;
    sm[t] = tot;
    __syncthreads();
    for (int off = 1; off < 1024; off <<= 1) {
        int v = (t >= off) ? sm[t - off] : 0;
        __syncthreads();
        sm[t] += v;
        __syncthreads();
    }
    int p = sm[t] - tot;  // exclusive prefix
    if (t == 1023) d_rowptr[NN] = sm[1023];
    for (int i = 0; i < NPG; i++) {
        int n = base + i;
        int dg = d_deg[n];
        d_rowptr[n] = p;
        d_csrc[p] = n;  // self loop
        float2 es = d_easum[n];
        float dd = (float)(dg > 0 ? dg : 1);
        d_cea[p] = make_float2(es.x / dd, es.y / dd);
        d_cur[n] = p + 1;
        p += dg + 1;
    }
}

__global__ void k_scatter(const int* __restrict__ ei, const float2* __restrict__ ea) {
    int e = blockIdx.x * blockDim.x + threadIdx.x;
    if (e >= NE) return;
    int d = ei[NE + e];
    int p = atomicAdd(&d_cur[d], 1);
    d_csrc[p] = ei[e];
    d_cea[p] = ea[e];
}

// ---------------- node transforms ----------------
// layer 0: h = x * W0 (x scalar per node); alpha via folded constants
__global__ void k_layer0(const float* __restrict__ x, const float* __restrict__ W0) {
    int lane = threadIdx.x & 31;
    int n = blockIdx.x * 8 + (threadIdx.x >> 5);
    float v = x[n];
    d_hB[n * H + lane] = v * W0[lane];
    if (lane == 0) { d_asrc[n] = v * d_c0[0]; d_adst[n] = v * d_c0[1]; }
}

// layers 1..3: h = hin @ W (32x32), alpha_src = h.a_s, alpha_dst = h.a_d
__global__ void k_mm(const float* __restrict__ hin, const float* __restrict__ W,
                     const float* __restrict__ a_s, const float* __restrict__ a_d,
                     float* __restrict__ hout) {
    __shared__ float Ws[H * H];
    __shared__ float As[H], Ad[H];
    int t = threadIdx.x;
    for (int i = t; i < H * H; i += 256) Ws[i] = W[i];
    if (t < H) { As[t] = a_s[t]; Ad[t] = a_d[t]; }
    __syncthreads();
    int lane = t & 31;
    int n = blockIdx.x * 8 + (t >> 5);
    float v = hin[n * H + lane];
    float o = 0.f;
    #pragma unroll
    for (int k = 0; k < H; k++)
        o = fmaf(__shfl_sync(~0u, v, k), Ws[k * H + lane], o);
    hout[n * H + lane] = o;
    float ps = o * As[lane], pd = o * Ad[lane];
    #pragma unroll
    for (int off = 16; off; off >>= 1) {
        ps += __shfl_xor_sync(~0u, ps, off);
        pd += __shfl_xor_sync(~0u, pd, off);
    }
    if (lane == 0) { d_asrc[n] = ps; d_adst[n] = pd; }
}

// ---------------- GAT softmax + aggregation: one warp per dst node ----------------
// lane = feature channel -> every h[src] gather is one coalesced 128B line.
// online softmax (m,s) per lane, warp-combined; logits register-cached for
// rows <= 128 edges (essentially all, deg ~ Poisson(48.75)); streaming fallback.
template<bool RELU>
__global__ void k_agg(const float* __restrict__ hlin, const float* __restrict__ bias,
                      int layer, float* __restrict__ hact) {
    int lane = threadIdx.x & 31;
    int n = blockIdx.x * 8 + (threadIdx.x >> 5);
    float2 ce = d_ce[layer];
    int rs = d_rowptr[n], re = d_rowptr[n + 1];
    float ad = d_adst[n];
    int len = re - rs;
    int nch = (len + 31) >> 5;
    bool fast = (nch <= 4);

    float m = BIG_NEG, s = 0.f;
    int sv[4]; float lv[4];

    if (fast) {
        #pragma unroll
        for (int c = 0; c < 4; c++) { sv[c] = 0; lv[c] = BIG_NEG; }
        #pragma unroll
        for (int c = 0; c < 4; c++) {
            if (c < nch) {
                int e = rs + c * 32 + lane;
                if (e < re) {
                    int srcn = d_csrc[e];
                    float2 a = d_cea[e];
                    float l = d_asrc[srcn] + ad + a.x * ce.x + a.y * ce.y;
                    l = (l >= 0.f) ? l : 0.2f * l;
                    sv[c] = srcn; lv[c] = l;
                    if (l > m) { s = s * __expf(m - l) + 1.f; m = l; }
                    else       { s += __expf(l - m); }
                }
            }
        }
    } else {
        for (int b = rs; b < re; b += 32) {
            int e = b + lane;
            if (e < re) {
                int srcn = d_csrc[e];
                float2 a = d_cea[e];
                float l = d_asrc[srcn] + ad + a.x * ce.x + a.y * ce.y;
                l = (l >= 0.f) ? l : 0.2f * l;
                if (l > m) { s = s * __expf(m - l) + 1.f; m = l; }
                else       { s += __expf(l - m); }
            }
        }
    }

    // warp-combine (m, s). BIG_NEG sentinel keeps everything finite (no inf/nan).
    #pragma unroll
    for (int off = 16; off; off >>= 1) {
        float mo = __shfl_xor_sync(~0u, m, off);
        float so = __shfl_xor_sync(~0u, s, off);
        float mn = fmaxf(m, mo);
        s = s * __expf(m - mn) + so * __expf(mo - mn);
        m = mn;
    }
    float inv_s = 1.f / s;  // row never empty (self-loop) -> s >= 1

    float acc = 0.f;
    if (fast) {
        #pragma unroll
        for (int c = 0; c < 4; c++) {
            if (c < nch) {
                float w = __expf(lv[c] - m) * inv_s;  // invalid lanes: exp(-1e30-m)=0
                int cnt = min(32, re - (rs + c * 32));
                if (cnt == 32) {
                    #pragma unroll
                    for (int j = 0; j < 32; j++) {
                        int   sj = __shfl_sync(~0u, sv[c], j);
                        float wj = __shfl_sync(~0u, w, j);
                        acc = fmaf(wj, hlin[sj * H + lane], acc);
                    }
                } else {
                    #pragma unroll 4
                    for (int j = 0; j < cnt; j++) {
                        int   sj = __shfl_sync(~0u, sv[c], j);
                        float wj = __shfl_sync(~0u, w, j);
                        acc = fmaf(wj, hlin[sj * H + lane], acc);
                    }
                }
            }
        }
    } else {
        for (int b = rs; b < re; b += 32) {
            int e = b + lane;
            float w = 0.f; int srcn = 0;
            if (e < re) {
                srcn = d_csrc[e];
                float2 a = d_cea[e];
                float l = d_asrc[srcn] + ad + a.x * ce.x + a.y * ce.y;
                l = (l >= 0.f) ? l : 0.2f * l;
                w = __expf(l - m) * inv_s;
            }
            int cnt = min(32, re - b);
            #pragma unroll 4
            for (int j = 0; j < cnt; j++) {
                int   sj = __shfl_sync(~0u, srcn, j);
                float wj = __shfl_sync(~0u, w, j);
                acc = fmaf(wj, hlin[sj * H + lane], acc);
            }
        }
    }

    float o = acc + bias[lane];
    if (RELU) o = fmaxf(o, 0.f);
    hact[n * H + lane] = o;
}

// ---------------- pool + linear + relu ----------------
__global__ void k_pool(const float* __restrict__ h, const float* __restrict__ lw,
                       const float* __restrict__ lb, float* __restrict__ out) {
    int lane = threadIdx.x & 31;
    int g = blockIdx.x * 8 + (threadIdx.x >> 5);
    if (g >= NG) return;
    const float* p = h + g * NPG * H;
    float acc = 0.f;
    #pragma unroll 6
    for (int r = 0; r < NPG; r++) acc += p[r * H + lane];
    float t = acc * lw[lane];
    #pragma unroll
    for (int off = 16; off; off >>= 1) t += __shfl_xor_sync(~0u, t, off);
    if (lane == 0) out[g] = fmaxf(t + lb[0], 0.f);
}

// ---------------- launch ----------------
extern "C" void kernel_launch(void* const* d_in, const int* in_sizes, int n_in,
                              void* d_out, int out_size) {
    const float*  x    = (const float*)d_in[0];
    const int*    ei   = (const int*)d_in[1];    // [2, E] int32
    const float2* ea   = (const float2*)d_in[2]; // [E, 2]
    const float*  W0   = (const float*)d_in[3];
    const float*  Ws   = (const float*)d_in[4];  // [3, 32, 32]
    const float*  as_  = (const float*)d_in[5];  // [4, 32]
    const float*  ad_  = (const float*)d_in[6];
    const float*  We   = (const float*)d_in[7];  // [4, 2, 32]
    const float*  ae_  = (const float*)d_in[8];
    const float*  bias = (const float*)d_in[9];  // [4, 32]
    const float*  lw   = (const float*)d_in[10]; // [32, 1]
    const float*  lb   = (const float*)d_in[11];
    float* out = (float*)d_out;

    float *hA, *hB;
    cudaGetSymbolAddress((void**)&hA, d_hA);
    cudaGetSymbolAddress((void**)&hB, d_hB);

    k_init<<<(NN + 255) / 256, 256>>>();
    k_consts<<<1, 160>>>(W0, as_, ad_, We, ae_);
    k_hist<<<NE / 256, 256>>>(ei, ea);
    k_scan<<<1, 1024>>>();
    k_scatter<<<NE / 256, 256>>>(ei, ea);

    k_layer0<<<NN / 8, 256>>>(x, W0);
    k_agg<true><<<NN / 8, 256>>>(hB, bias + 0, 0, hA);
    for (int l = 1; l < 4; l++) {
        k_mm<<<NN / 8, 256>>>(hA, Ws + (l - 1) * H * H, as_ + l * H, ad_ + l * H, hB);
        if (l < 3) k_agg<true ><<<NN / 8, 256>>>(hB, bias + l * H, l, hA);
        else       k_agg<false><<<NN / 8, 256>>>(hB, bias + l * H, l, hA);
    }
    k_pool<<<128, 256>>>(hA, lw, lb, out);
}

// round 2
// speedup vs baseline: 1.4214x; 1.4214x over previous
#include <cuda_runtime.h>

#define NN 86016
#define NE 4194304
#define H 32
#define NG 1024
#define NPG 84
#define ETOT (NE + NN)
#define NBLK 84            // NN / 1024
#define BIG_NEG -1e30f

// ---------------- device scratch (no allocations allowed) ----------------
__device__ int    d_deg[NN];
__device__ float2 d_easum[NN];
__device__ int    d_cur[NN];
__device__ int    d_rowptr[NN + 1];
__device__ int    d_rowloc[NN];     // exclusive prefix within 1024-block
__device__ int    d_blksum[NBLK];
__device__ int    d_blkoff[NBLK];
__device__ int    d_csrc[ETOT];
__device__ float2 d_cea[ETOT];
__device__ float  d_hA[NN * H];
__device__ float  d_hB[NN * H];
__device__ float  d_asrc[NN];
__device__ float  d_adst[NN];
__device__ float2 d_ce[4];
__device__ float  d_c0[2];

// ---------------- init ----------------
__global__ void k_init() {
    int i = blockIdx.x * blockDim.x + threadIdx.x;
    if (i < NN) { d_deg[i] = 0; d_easum[i] = make_float2(0.f, 0.f); }
}

// per-layer folded constants: ce[l] = We[l] @ att_edge[l]; c0 = (W0.a_s, W0.a_d)
__global__ void k_consts(const float* __restrict__ W0, const float* __restrict__ a_s,
                         const float* __restrict__ a_d, const float* __restrict__ We,
                         const float* __restrict__ a_e) {
    int w = threadIdx.x >> 5, lane = threadIdx.x & 31;
    if (w < 4) {
        float ae = a_e[w * 32 + lane];
        float p0 = We[w * 64 + lane] * ae;
        float p1 = We[w * 64 + 32 + lane] * ae;
        #pragma unroll
        for (int o = 16; o; o >>= 1) {
            p0 += __shfl_xor_sync(~0u, p0, o);
            p1 += __shfl_xor_sync(~0u, p1, o);
        }
        if (lane == 0) d_ce[w] = make_float2(p0, p1);
    } else {
        float w0 = W0[lane];
        float ps = w0 * a_s[lane];
        float pd = w0 * a_d[lane];
        #pragma unroll
        for (int o = 16; o; o >>= 1) {
            ps += __shfl_xor_sync(~0u, ps, o);
            pd += __shfl_xor_sync(~0u, pd, o);
        }
        if (lane == 0) { d_c0[0] = ps; d_c0[1] = pd; }
    }
}

// ---------------- CSR build ----------------
__global__ void k_hist(const int* __restrict__ ei, const float2* __restrict__ ea) {
    int e2 = blockIdx.x * blockDim.x + threadIdx.x;   // handles 2 edges
    int e = e2 * 2;
    if (e >= NE) return;
    int2 d = *(const int2*)(ei + NE + e);
    float2 a0 = ea[e], a1 = ea[e + 1];
    atomicAdd(&d_deg[d.x], 1);
    atomicAdd(&d_easum[d.x].x, a0.x);
    atomicAdd(&d_easum[d.x].y, a0.y);
    atomicAdd(&d_deg[d.y], 1);
    atomicAdd(&d_easum[d.y].x, a1.x);
    atomicAdd(&d_easum[d.y].y, a1.y);
}

// phase A: per-1024-block inclusive scan of (deg+1); store local exclusive
// prefix per node and per-block total.
__global__ void k_scanA() {
    __shared__ int sm[1024];
    int t = threadIdx.x;
    int n = blockIdx.x * 1024 + t;
    int sz = d_deg[n] + 1;
    sm[t] = sz;
    __syncthreads();
    #pragma unroll
    for (int off = 1; off < 1024; off <<= 1) {
        int v = (t >= off) ? sm[t - off] : 0;
        __syncthreads();
        sm[t] += v;
        __syncthreads();
    }
    d_rowloc[n] = sm[t] - sz;
    if (t == 1023) d_blksum[blockIdx.x] = sm[1023];
}

// phase B: scan the 84 block totals (single warp)
__global__ void k_scanB() {
    if (threadIdx.x == 0) {
        int acc = 0;
        #pragma unroll 4
        for (int b = 0; b < NBLK; b++) { d_blkoff[b] = acc; acc += d_blksum[b]; }
    }
}

// phase C: final rowptr + self-loop entry + cursor, one thread per node
__global__ void k_scanC() {
    int n = blockIdx.x * blockDim.x + threadIdx.x;
    if (n >= NN) return;
    int p = d_rowloc[n] + d_blkoff[n >> 10];
    d_rowptr[n] = p;
    if (n == 0) d_rowptr[NN] = ETOT;
    d_csrc[p] = n;  // self loop
    int dg = d_deg[n];
    float2 es = d_easum[n];
    float dd = (float)(dg > 0 ? dg : 1);
    d_cea[p] = make_float2(es.x / dd, es.y / dd);
    d_cur[n] = p + 1;
}

__global__ void k_scatter(const int* __restrict__ ei, const float2* __restrict__ ea) {
    int e2 = blockIdx.x * blockDim.x + threadIdx.x;
    int e = e2 * 2;
    if (e >= NE) return;
    int2 s = *(const int2*)(ei + e);
    int2 d = *(const int2*)(ei + NE + e);
    float2 a0 = ea[e], a1 = ea[e + 1];
    int p0 = atomicAdd(&d_cur[d.x], 1);
    d_csrc[p0] = s.x;
    d_cea[p0] = a0;
    int p1 = atomicAdd(&d_cur[d.y], 1);
    d_csrc[p1] = s.y;
    d_cea[p1] = a1;
}

// ---------------- node transforms ----------------
__global__ void k_layer0(const float* __restrict__ x, const float* __restrict__ W0) {
    int lane = threadIdx.x & 31;
    int n = blockIdx.x * 8 + (threadIdx.x >> 5);
    float v = x[n];
    d_hB[n * H + lane] = v * W0[lane];
    if (lane == 0) { d_asrc[n] = v * d_c0[0]; d_adst[n] = v * d_c0[1]; }
}

__global__ void k_mm(const float* __restrict__ hin, const float* __restrict__ W,
                     const float* __restrict__ a_s, const float* __restrict__ a_d,
                     float* __restrict__ hout) {
    __shared__ float Ws[H * H];
    __shared__ float As[H], Ad[H];
    int t = threadIdx.x;
    for (int i = t; i < H * H; i += 256) Ws[i] = W[i];
    if (t < H) { As[t] = a_s[t]; Ad[t] = a_d[t]; }
    __syncthreads();
    int lane = t & 31;
    int n = blockIdx.x * 8 + (t >> 5);
    float v = hin[n * H + lane];
    float o = 0.f;
    #pragma unroll
    for (int k = 0; k < H; k++)
        o = fmaf(__shfl_sync(~0u, v, k), Ws[k * H + lane], o);
    hout[n * H + lane] = o;
    float ps = o * As[lane], pd = o * Ad[lane];
    #pragma unroll
    for (int off = 16; off; off >>= 1) {
        ps += __shfl_xor_sync(~0u, ps, off);
        pd += __shfl_xor_sync(~0u, pd, off);
    }
    if (lane == 0) { d_asrc[n] = ps; d_adst[n] = pd; }
}

// ---------------- GAT softmax + aggregation: one warp per dst node ----------------
template<bool RELU>
__global__ void k_agg(const float* __restrict__ hlin, const float* __restrict__ bias,
                      int layer, float* __restrict__ hact) {
    int lane = threadIdx.x & 31;
    int n = blockIdx.x * 8 + (threadIdx.x >> 5);
    float2 ce = d_ce[layer];
    int rs = d_rowptr[n], re = d_rowptr[n + 1];
    float ad = d_adst[n];
    int len = re - rs;
    int nch = (len + 31) >> 5;
    bool fast = (nch <= 4);

    float m = BIG_NEG, s = 0.f;
    int sv[4]; float lv[4];

    if (fast) {
        #pragma unroll
        for (int c = 0; c < 4; c++) { sv[c] = 0; lv[c] = BIG_NEG; }
        #pragma unroll
        for (int c = 0; c < 4; c++) {
            if (c < nch) {
                int e = rs + c * 32 + lane;
                if (e < re) {
                    int srcn = d_csrc[e];
                    float2 a = d_cea[e];
                    float l = d_asrc[srcn] + ad + a.x * ce.x + a.y * ce.y;
                    l = (l >= 0.f) ? l : 0.2f * l;
                    sv[c] = srcn; lv[c] = l;
                    if (l > m) { s = s * __expf(m - l) + 1.f; m = l; }
                    else       { s += __expf(l - m); }
                }
            }
        }
    } else {
        for (int b = rs; b < re; b += 32) {
            int e = b + lane;
            if (e < re) {
                int srcn = d_csrc[e];
                float2 a = d_cea[e];
                float l = d_asrc[srcn] + ad + a.x * ce.x + a.y * ce.y;
                l = (l >= 0.f) ? l : 0.2f * l;
                if (l > m) { s = s * __expf(m - l) + 1.f; m = l; }
                else       { s += __expf(l - m); }
            }
        }
    }

    #pragma unroll
    for (int off = 16; off; off >>= 1) {
        float mo = __shfl_xor_sync(~0u, m, off);
        float so = __shfl_xor_sync(~0u, s, off);
        float mn = fmaxf(m, mo);
        s = s * __expf(m - mn) + so * __expf(mo - mn);
        m = mn;
    }
    float inv_s = 1.f / s;

    float acc = 0.f;
    if (fast) {
        #pragma unroll
        for (int c = 0; c < 4; c++) {
            if (c < nch) {
                float w = __expf(lv[c] - m) * inv_s;
                int cnt = min(32, re - (rs + c * 32));
                if (cnt == 32) {
                    #pragma unroll
                    for (int j = 0; j < 32; j++) {
                        int   sj = __shfl_sync(~0u, sv[c], j);
                        float wj = __shfl_sync(~0u, w, j);
                        acc = fmaf(wj, hlin[sj * H + lane], acc);
                    }
                } else {
                    #pragma unroll 4
                    for (int j = 0; j < cnt; j++) {
                        int   sj = __shfl_sync(~0u, sv[c], j);
                        float wj = __shfl_sync(~0u, w, j);
                        acc = fmaf(wj, hlin[sj * H + lane], acc);
                    }
                }
            }
        }
    } else {
        for (int b = rs; b < re; b += 32) {
            int e = b + lane;
            float w = 0.f; int srcn = 0;
            if (e < re) {
                srcn = d_csrc[e];
                float2 a = d_cea[e];
                float l = d_asrc[srcn] + ad + a.x * ce.x + a.y * ce.y;
                l = (l >= 0.f) ? l : 0.2f * l;
                w = __expf(l - m) * inv_s;
            }
            int cnt = min(32, re - b);
            #pragma unroll 4
            for (int j = 0; j < cnt; j++) {
                int   sj = __shfl_sync(~0u, srcn, j);
                float wj = __shfl_sync(~0u, w, j);
                acc = fmaf(wj, hlin[sj * H + lane], acc);
            }
        }
    }

    float o = acc + bias[lane];
    if (RELU) o = fmaxf(o, 0.f);
    hact[n * H + lane] = o;
}

// ---------------- pool + linear + relu ----------------
__global__ void k_pool(const float* __restrict__ h, const float* __restrict__ lw,
                       const float* __restrict__ lb, float* __restrict__ out) {
    int lane = threadIdx.x & 31;
    int g = blockIdx.x * 8 + (threadIdx.x >> 5);
    if (g >= NG) return;
    const float* p = h + g * NPG * H;
    float acc = 0.f;
    #pragma unroll 6
    for (int r = 0; r < NPG; r++) acc += p[r * H + lane];
    float t = acc * lw[lane];
    #pragma unroll
    for (int off = 16; off; off >>= 1) t += __shfl_xor_sync(~0u, t, off);
    if (lane == 0) out[g] = fmaxf(t + lb[0], 0.f);
}

// ---------------- launch ----------------
extern "C" void kernel_launch(void* const* d_in, const int* in_sizes, int n_in,
                              void* d_out, int out_size) {
    const float*  x    = (const float*)d_in[0];
    const int*    ei   = (const int*)d_in[1];
    const float2* ea   = (const float2*)d_in[2];
    const float*  W0   = (const float*)d_in[3];
    const float*  Ws   = (const float*)d_in[4];
    const float*  as_  = (const float*)d_in[5];
    const float*  ad_  = (const float*)d_in[6];
    const float*  We   = (const float*)d_in[7];
    const float*  ae_  = (const float*)d_in[8];
    const float*  bias = (const float*)d_in[9];
    const float*  lw   = (const float*)d_in[10];
    const float*  lb   = (const float*)d_in[11];
    float* out = (float*)d_out;

    float *hA, *hB;
    cudaGetSymbolAddress((void**)&hA, d_hA);
    cudaGetSymbolAddress((void**)&hB, d_hB);

    k_init<<<(NN + 255) / 256, 256>>>();
    k_consts<<<1, 160>>>(W0, as_, ad_, We, ae_);
    k_hist<<<NE / 512, 256>>>(ei, ea);
    k_scanA<<<NBLK, 1024>>>();
    k_scanB<<<1, 32>>>();
    k_scanC<<<(NN + 255) / 256, 256>>>();
    k_scatter<<<NE / 512, 256>>>(ei, ea);

    k_layer0<<<NN / 8, 256>>>(x, W0);
    k_agg<true><<<NN / 8, 256>>>(hB, bias + 0, 0, hA);
    for (int l = 1; l < 4; l++) {
        k_mm<<<NN / 8, 256>>>(hA, Ws + (l - 1) * H * H, as_ + l * H, ad_ + l * H, hB);
        if (l < 3) k_agg<true ><<<NN / 8, 256>>>(hB, bias + l * H, l, hA);
        else       k_agg<false><<<NN / 8, 256>>>(hB, bias + l * H, l, hA);
    }
    k_pool<<<128, 256>>>(hA, lw, lb, out);
}

// round 3
// speedup vs baseline: 1.5702x; 1.1047x over previous
#include <cuda_runtime.h>

#define NN 86016
#define NE 4194304
#define H 32
#define NG 1024
#define NPG 84
#define ETOT (NE + NN)
#define NBLK 84            // NN / 1024
#define BIG_NEG -1e30f

// ---------------- device scratch ----------------
__device__ int    d_deg[NN];
__device__ int    d_cur[NN];
__device__ int    d_rowptr[NN + 1];
__device__ int    d_rowloc[NN];
__device__ int    d_blksum[NBLK];
__device__ int    d_blkoff[NBLK];
__device__ int    d_csrc[ETOT];
__device__ float2 d_cea[ETOT];
__device__ float  d_hA[NN * H];
__device__ float  d_hB[NN * H];
__device__ float  d_asrcA[NN], d_adstA[NN];
__device__ float  d_asrcB[NN], d_adstB[NN];
__device__ float2 d_ce[4];
__device__ float  d_c0[2];

// ---------------- init ----------------
__global__ void k_init() {
    int i = blockIdx.x * blockDim.x + threadIdx.x;
    if (i < NN) d_deg[i] = 0;
}

// folded constants: ce[l] = We[l] @ att_edge[l]; c0 = (W0.a_s, W0.a_d)
__global__ void k_consts(const float* __restrict__ W0, const float* __restrict__ a_s,
                         const float* __restrict__ a_d, const float* __restrict__ We,
                         const float* __restrict__ a_e) {
    int w = threadIdx.x >> 5, lane = threadIdx.x & 31;
    if (w < 4) {
        float ae = a_e[w * 32 + lane];
        float p0 = We[w * 64 + lane] * ae;
        float p1 = We[w * 64 + 32 + lane] * ae;
        #pragma unroll
        for (int o = 16; o; o >>= 1) {
            p0 += __shfl_xor_sync(~0u, p0, o);
            p1 += __shfl_xor_sync(~0u, p1, o);
        }
        if (lane == 0) d_ce[w] = make_float2(p0, p1);
    } else {
        float w0 = W0[lane];
        float ps = w0 * a_s[lane];
        float pd = w0 * a_d[lane];
        #pragma unroll
        for (int o = 16; o; o >>= 1) {
            ps += __shfl_xor_sync(~0u, ps, o);
            pd += __shfl_xor_sync(~0u, pd, o);
        }
        if (lane == 0) { d_c0[0] = ps; d_c0[1] = pd; }
    }
}

// ---------------- CSR build ----------------
// hist: deg only, 4 edges/thread
__global__ void k_hist(const int* __restrict__ ei) {
    int e4 = blockIdx.x * blockDim.x + threadIdx.x;
    int e = e4 * 4;
    if (e >= NE) return;
    int4 d = *(const int4*)(ei + NE + e);
    atomicAdd(&d_deg[d.x], 1);
    atomicAdd(&d_deg[d.y], 1);
    atomicAdd(&d_deg[d.z], 1);
    atomicAdd(&d_deg[d.w], 1);
}

__global__ void k_scanA() {
    __shared__ int sm[1024];
    int t = threadIdx.x;
    int n = blockIdx.x * 1024 + t;
    int sz = d_deg[n] + 1;
    sm[t] = sz;
    __syncthreads();
    #pragma unroll
    for (int off = 1; off < 1024; off <<= 1) {
        int v = (t >= off) ? sm[t - off] : 0;
        __syncthreads();
        sm[t] += v;
        __syncthreads();
    }
    d_rowloc[n] = sm[t] - sz;
    if (t == 1023) d_blksum[blockIdx.x] = sm[1023];
}

__global__ void k_scanB() {
    if (threadIdx.x == 0) {
        int acc = 0;
        #pragma unroll 4
        for (int b = 0; b < NBLK; b++) { d_blkoff[b] = acc; acc += d_blksum[b]; }
    }
}

// rowptr + self-loop src + cursor (self-loop cea filled later by k_loop)
__global__ void k_scanC() {
    int n = blockIdx.x * blockDim.x + threadIdx.x;
    if (n >= NN) return;
    int p = d_rowloc[n] + d_blkoff[n >> 10];
    d_rowptr[n] = p;
    if (n == 0) d_rowptr[NN] = ETOT;
    d_csrc[p] = n;
    d_cur[n] = p + 1;
}

__global__ void k_scatter(const int* __restrict__ ei, const float2* __restrict__ ea) {
    int e4 = blockIdx.x * blockDim.x + threadIdx.x;
    int e = e4 * 4;
    if (e >= NE) return;
    int4 s = *(const int4*)(ei + e);
    int4 d = *(const int4*)(ei + NE + e);
    float4 a01 = *(const float4*)(ea + e);
    float4 a23 = *(const float4*)(ea + e + 2);
    int p;
    p = atomicAdd(&d_cur[d.x], 1); d_csrc[p] = s.x; d_cea[p] = make_float2(a01.x, a01.y);
    p = atomicAdd(&d_cur[d.y], 1); d_csrc[p] = s.y; d_cea[p] = make_float2(a01.z, a01.w);
    p = atomicAdd(&d_cur[d.z], 1); d_csrc[p] = s.z; d_cea[p] = make_float2(a23.x, a23.y);
    p = atomicAdd(&d_cur[d.w], 1); d_csrc[p] = s.w; d_cea[p] = make_float2(a23.z, a23.w);
}

// self-loop edge attr = mean of incoming edge attrs (coalesced row sum)
__global__ void k_loop() {
    int lane = threadIdx.x & 31;
    int n = blockIdx.x * 8 + (threadIdx.x >> 5);
    int rs = d_rowptr[n], re = d_rowptr[n + 1];
    float sx = 0.f, sy = 0.f;
    for (int e = rs + 1 + lane; e < re; e += 32) {
        float2 a = d_cea[e];
        sx += a.x; sy += a.y;
    }
    #pragma unroll
    for (int off = 16; off; off >>= 1) {
        sx += __shfl_xor_sync(~0u, sx, off);
        sy += __shfl_xor_sync(~0u, sy, off);
    }
    if (lane == 0) {
        int dg = re - rs - 1;
        float dd = (float)(dg > 0 ? dg : 1);
        d_cea[rs] = make_float2(sx / dd, sy / dd);
    }
}

// ---------------- layer 0 node transform ----------------
__global__ void k_layer0(const float* __restrict__ x, const float* __restrict__ W0) {
    int lane = threadIdx.x & 31;
    int n = blockIdx.x * 8 + (threadIdx.x >> 5);
    float v = x[n];
    d_hB[n * H + lane] = v * W0[lane];
    if (lane == 0) { d_asrcA[n] = v * d_c0[0]; d_adstA[n] = v * d_c0[1]; }
}

// ---------------- GAT agg (+ fused next-layer transform) ----------------
// FUSED=1: epilogue applies Wnext, writes next-layer h + asrc/adst.
// FUSED=0: last layer, writes aggregated h (no relu).
template<int FUSED>
__global__ void k_agg(const float* __restrict__ hlin,
                      const float* __restrict__ bias, int layer,
                      const float* __restrict__ Wn, const float* __restrict__ asn,
                      const float* __restrict__ adn,
                      const float* __restrict__ asrc_in, const float* __restrict__ adst_in,
                      float* __restrict__ hout,
                      float* __restrict__ asrc_out, float* __restrict__ adst_out) {
    __shared__ float Ws[H * H];
    __shared__ float As[H], Ad[H];
    int t = threadIdx.x;
    if (FUSED) {
        for (int i = t; i < H * H; i += 256) Ws[i] = Wn[i];
        if (t < H) { As[t] = asn[t]; Ad[t] = adn[t]; }
        __syncthreads();
    }

    int lane = t & 31;
    int n = blockIdx.x * 8 + (t >> 5);
    float2 ce = d_ce[layer];
    int rs = d_rowptr[n], re = d_rowptr[n + 1];
    float ad = adst_in[n];
    int len = re - rs;
    int nch = (len + 31) >> 5;
    bool fast = (nch <= 4);

    float m = BIG_NEG, s = 0.f;
    int sv[4]; float lv[4];

    if (fast) {
        #pragma unroll
        for (int c = 0; c < 4; c++) { sv[c] = 0; lv[c] = BIG_NEG; }
        #pragma unroll
        for (int c = 0; c < 4; c++) {
            if (c < nch) {
                int e = rs + c * 32 + lane;
                if (e < re) {
                    int srcn = d_csrc[e];
                    float2 a = d_cea[e];
                    float l = asrc_in[srcn] + ad + a.x * ce.x + a.y * ce.y;
                    l = (l >= 0.f) ? l : 0.2f * l;
                    sv[c] = srcn; lv[c] = l;
                    if (l > m) { s = s * __expf(m - l) + 1.f; m = l; }
                    else       { s += __expf(l - m); }
                }
            }
        }
    } else {
        for (int b = rs; b < re; b += 32) {
            int e = b + lane;
            if (e < re) {
                int srcn = d_csrc[e];
                float2 a = d_cea[e];
                float l = asrc_in[srcn] + ad + a.x * ce.x + a.y * ce.y;
                l = (l >= 0.f) ? l : 0.2f * l;
                if (l > m) { s = s * __expf(m - l) + 1.f; m = l; }
                else       { s += __expf(l - m); }
            }
        }
    }

    #pragma unroll
    for (int off = 16; off; off >>= 1) {
        float mo = __shfl_xor_sync(~0u, m, off);
        float so = __shfl_xor_sync(~0u, s, off);
        float mn = fmaxf(m, mo);
        s = s * __expf(m - mn) + so * __expf(mo - mn);
        m = mn;
    }
    float inv_s = 1.f / s;

    float acc0 = 0.f, acc1 = 0.f;
    if (fast) {
        #pragma unroll
        for (int c = 0; c < 4; c++) {
            if (c < nch) {
                float w = __expf(lv[c] - m) * inv_s;
                int cnt = min(32, re - (rs + c * 32));
                if (cnt == 32) {
                    #pragma unroll
                    for (int j = 0; j < 32; j += 2) {
                        int   s0 = __shfl_sync(~0u, sv[c], j);
                        float w0 = __shfl_sync(~0u, w, j);
                        int   s1 = __shfl_sync(~0u, sv[c], j + 1);
                        float w1 = __shfl_sync(~0u, w, j + 1);
                        acc0 = fmaf(w0, hlin[s0 * H + lane], acc0);
                        acc1 = fmaf(w1, hlin[s1 * H + lane], acc1);
                    }
                } else {
                    #pragma unroll 4
                    for (int j = 0; j < cnt; j++) {
                        int   sj = __shfl_sync(~0u, sv[c], j);
                        float wj = __shfl_sync(~0u, w, j);
                        acc0 = fmaf(wj, hlin[sj * H + lane], acc0);
                    }
                }
            }
        }
    } else {
        for (int b = rs; b < re; b += 32) {
            int e = b + lane;
            float w = 0.f; int srcn = 0;
            if (e < re) {
                srcn = d_csrc[e];
                float2 a = d_cea[e];
                float l = asrc_in[srcn] + ad + a.x * ce.x + a.y * ce.y;
                l = (l >= 0.f) ? l : 0.2f * l;
                w = __expf(l - m) * inv_s;
            }
            int cnt = min(32, re - b);
            #pragma unroll 4
            for (int j = 0; j < cnt; j++) {
                int   sj = __shfl_sync(~0u, srcn, j);
                float wj = __shfl_sync(~0u, w, j);
                acc0 = fmaf(wj, hlin[sj * H + lane], acc0);
            }
        }
    }

    float o = acc0 + acc1 + bias[lane];
    if (FUSED) {
        o = fmaxf(o, 0.f);  // relu
        // next-layer transform: hn = o @ Wn; alphas
        float hn = 0.f;
        #pragma unroll
        for (int k = 0; k < H; k++)
            hn = fmaf(__shfl_sync(~0u, o, k), Ws[k * H + lane], hn);
        hout[n * H + lane] = hn;
        float ps = hn * As[lane], pd = hn * Ad[lane];
        #pragma unroll
        for (int off = 16; off; off >>= 1) {
            ps += __shfl_xor_sync(~0u, ps, off);
            pd += __shfl_xor_sync(~0u, pd, off);
        }
        if (lane == 0) { asrc_out[n] = ps; adst_out[n] = pd; }
    } else {
        hout[n * H + lane] = o;  // last layer: no relu
    }
}

// ---------------- pool + linear + relu ----------------
__global__ void k_pool(const float* __restrict__ h, const float* __restrict__ lw,
                       const float* __restrict__ lb, float* __restrict__ out) {
    int lane = threadIdx.x & 31;
    int g = blockIdx.x * 8 + (threadIdx.x >> 5);
    if (g >= NG) return;
    const float* p = h + g * NPG * H;
    float acc = 0.f;
    #pragma unroll 6
    for (int r = 0; r < NPG; r++) acc += p[r * H + lane];
    float t = acc * lw[lane];
    #pragma unroll
    for (int off = 16; off; off >>= 1) t += __shfl_xor_sync(~0u, t, off);
    if (lane == 0) out[g] = fmaxf(t + lb[0], 0.f);
}

// ---------------- launch ----------------
extern "C" void kernel_launch(void* const* d_in, const int* in_sizes, int n_in,
                              void* d_out, int out_size) {
    const float*  x    = (const float*)d_in[0];
    const int*    ei   = (const int*)d_in[1];
    const float2* ea   = (const float2*)d_in[2];
    const float*  W0   = (const float*)d_in[3];
    const float*  Ws   = (const float*)d_in[4];
    const float*  as_  = (const float*)d_in[5];
    const float*  ad_  = (const float*)d_in[6];
    const float*  We   = (const float*)d_in[7];
    const float*  ae_  = (const float*)d_in[8];
    const float*  bias = (const float*)d_in[9];
    const float*  lw   = (const float*)d_in[10];
    const float*  lb   = (const float*)d_in[11];
    float* out = (float*)d_out;

    float *hA, *hB, *asA, *adA, *asB, *adB;
    cudaGetSymbolAddress((void**)&hA, d_hA);
    cudaGetSymbolAddress((void**)&hB, d_hB);
    cudaGetSymbolAddress((void**)&asA, d_asrcA);
    cudaGetSymbolAddress((void**)&adA, d_adstA);
    cudaGetSymbolAddress((void**)&asB, d_asrcB);
    cudaGetSymbolAddress((void**)&adB, d_adstB);

    k_init<<<(NN + 255) / 256, 256>>>();
    k_consts<<<1, 160>>>(W0, as_, ad_, We, ae_);
    k_hist<<<NE / 1024, 256>>>(ei);
    k_scanA<<<NBLK, 1024>>>();
    k_scanB<<<1, 32>>>();
    k_scanC<<<(NN + 255) / 256, 256>>>();
    k_scatter<<<NE / 1024, 256>>>(ei, ea);
    k_loop<<<NN / 8, 256>>>();

    k_layer0<<<NN / 8, 256>>>(x, W0);
    // agg l reads {h,asrc,adst} of layer l, epilogue computes layer l+1 inputs
    k_agg<1><<<NN / 8, 256>>>(hB, bias + 0 * H, 0, Ws + 0 * H * H, as_ + 1 * H, ad_ + 1 * H,
                              asA, adA, hA, asB, adB);
    k_agg<1><<<NN / 8, 256>>>(hA, bias + 1 * H, 1, Ws + 1 * H * H, as_ + 2 * H, ad_ + 2 * H,
                              asB, adB, hB, asA, adA);
    k_agg<1><<<NN / 8, 256>>>(hB, bias + 2 * H, 2, Ws + 2 * H * H, as_ + 3 * H, ad_ + 3 * H,
                              asA, adA, hA, asB, adB);
    k_agg<0><<<NN / 8, 256>>>(hA, bias + 3 * H, 3, nullptr, nullptr, nullptr,
                              asB, adB, hB, nullptr, nullptr);
    k_pool<<<128, 256>>>(hB, lw, lb, out);
}

// round 4
// speedup vs baseline: 1.6006x; 1.0193x over previous
#include <cuda_runtime.h>
#include <cuda_fp16.h>

#define NN 86016
#define NE 4194304
#define H 32
#define NG 1024
#define NPG 84
#define ETOT (NE + NN)
#define NBLK 84
#define BIG_NEG -1e30f

// 16B CSR entry: one sector per scatter write
struct __align__(16) Ent { int src; int pad; float ex; float ey; };

// ---------------- device scratch ----------------
__device__ int    d_deg[NN];
__device__ int    d_cur[NN];
__device__ int    d_rowptr[NN + 1];
__device__ int    d_rowloc[NN];
__device__ int    d_blksum[NBLK];
__device__ int    d_blkoff[NBLK];
__device__ Ent    d_ent[ETOT];
__device__ __half d_h16A[NN * H];
__device__ __half d_h16B[NN * H];
__device__ float  d_hfin[NN * H];
__device__ float  d_asrcA[NN], d_adstA[NN];
__device__ float  d_asrcB[NN], d_adstB[NN];
__device__ float2 d_ce[4];
__device__ float  d_c0[2];

// ---------------- init ----------------
__global__ void k_init() {
    int i = blockIdx.x * blockDim.x + threadIdx.x;
    if (i < NN) d_deg[i] = 0;
}

__global__ void k_consts(const float* __restrict__ W0, const float* __restrict__ a_s,
                         const float* __restrict__ a_d, const float* __restrict__ We,
                         const float* __restrict__ a_e) {
    int w = threadIdx.x >> 5, lane = threadIdx.x & 31;
    if (w < 4) {
        float ae = a_e[w * 32 + lane];
        float p0 = We[w * 64 + lane] * ae;
        float p1 = We[w * 64 + 32 + lane] * ae;
        #pragma unroll
        for (int o = 16; o; o >>= 1) {
            p0 += __shfl_xor_sync(~0u, p0, o);
            p1 += __shfl_xor_sync(~0u, p1, o);
        }
        if (lane == 0) d_ce[w] = make_float2(p0, p1);
    } else {
        float w0 = W0[lane];
        float ps = w0 * a_s[lane];
        float pd = w0 * a_d[lane];
        #pragma unroll
        for (int o = 16; o; o >>= 1) {
            ps += __shfl_xor_sync(~0u, ps, o);
            pd += __shfl_xor_sync(~0u, pd, o);
        }
        if (lane == 0) { d_c0[0] = ps; d_c0[1] = pd; }
    }
}

// ---------------- CSR build ----------------
__global__ void k_hist(const int* __restrict__ ei) {
    int e4 = blockIdx.x * blockDim.x + threadIdx.x;
    int e = e4 * 4;
    if (e >= NE) return;
    int4 d = *(const int4*)(ei + NE + e);
    atomicAdd(&d_deg[d.x], 1);
    atomicAdd(&d_deg[d.y], 1);
    atomicAdd(&d_deg[d.z], 1);
    atomicAdd(&d_deg[d.w], 1);
}

__global__ void k_scanA() {
    __shared__ int sm[1024];
    int t = threadIdx.x;
    int n = blockIdx.x * 1024 + t;
    int sz = d_deg[n] + 1;
    sm[t] = sz;
    __syncthreads();
    #pragma unroll
    for (int off = 1; off < 1024; off <<= 1) {
        int v = (t >= off) ? sm[t - off] : 0;
        __syncthreads();
        sm[t] += v;
        __syncthreads();
    }
    d_rowloc[n] = sm[t] - sz;
    if (t == 1023) d_blksum[blockIdx.x] = sm[1023];
}

__global__ void k_scanB() {
    if (threadIdx.x == 0) {
        int acc = 0;
        #pragma unroll 4
        for (int b = 0; b < NBLK; b++) { d_blkoff[b] = acc; acc += d_blksum[b]; }
    }
}

__global__ void k_scanC() {
    int n = blockIdx.x * blockDim.x + threadIdx.x;
    if (n >= NN) return;
    int p = d_rowloc[n] + d_blkoff[n >> 10];
    d_rowptr[n] = p;
    if (n == 0) d_rowptr[NN] = ETOT;
    d_ent[p].src = n;          // self loop
    d_cur[n] = p + 1;
}

__global__ void k_scatter(const int* __restrict__ ei, const float2* __restrict__ ea) {
    int e4 = blockIdx.x * blockDim.x + threadIdx.x;
    int e = e4 * 4;
    if (e >= NE) return;
    int4 s = *(const int4*)(ei + e);
    int4 d = *(const int4*)(ei + NE + e);
    float4 a01 = *(const float4*)(ea + e);
    float4 a23 = *(const float4*)(ea + e + 2);
    int4* ent = (int4*)d_ent;
    int p;
    p = atomicAdd(&d_cur[d.x], 1);
    ent[p] = make_int4(s.x, 0, __float_as_int(a01.x), __float_as_int(a01.y));
    p = atomicAdd(&d_cur[d.y], 1);
    ent[p] = make_int4(s.y, 0, __float_as_int(a01.z), __float_as_int(a01.w));
    p = atomicAdd(&d_cur[d.z], 1);
    ent[p] = make_int4(s.z, 0, __float_as_int(a23.x), __float_as_int(a23.y));
    p = atomicAdd(&d_cur[d.w], 1);
    ent[p] = make_int4(s.w, 0, __float_as_int(a23.z), __float_as_int(a23.w));
}

// self-loop edge attr = mean of incoming edge attrs
__global__ void k_loop() {
    int lane = threadIdx.x & 31;
    int n = blockIdx.x * 8 + (threadIdx.x >> 5);
    int rs = d_rowptr[n], re = d_rowptr[n + 1];
    float sx = 0.f, sy = 0.f;
    for (int e = rs + 1 + lane; e < re; e += 32) {
        sx += d_ent[e].ex; sy += d_ent[e].ey;
    }
    #pragma unroll
    for (int off = 16; off; off >>= 1) {
        sx += __shfl_xor_sync(~0u, sx, off);
        sy += __shfl_xor_sync(~0u, sy, off);
    }
    if (lane == 0) {
        int dg = re - rs - 1;
        float dd = (float)(dg > 0 ? dg : 1);
        d_ent[rs].ex = sx / dd;
        d_ent[rs].ey = sy / dd;
    }
}

// ---------------- layer 0 node transform ----------------
__global__ void k_layer0(const float* __restrict__ x, const float* __restrict__ W0) {
    int lane = threadIdx.x & 31;
    int n = blockIdx.x * 8 + (threadIdx.x >> 5);
    float v = x[n];
    d_h16B[n * H + lane] = __float2half(v * W0[lane]);
    if (lane == 0) { d_asrcA[n] = v * d_c0[0]; d_adstA[n] = v * d_c0[1]; }
}

// ---------------- GAT agg (+ fused next-layer transform) ----------------
// FUSED=1: relu, apply Wnext, write next-layer h (fp16) + asrc/adst (fp32).
// FUSED=0: last layer, write aggregated h to fp32 buffer.
template<int FUSED>
__global__ void k_agg(const __half* __restrict__ hlin,
                      const float* __restrict__ bias, int layer,
                      const float* __restrict__ Wn, const float* __restrict__ asn,
                      const float* __restrict__ adn,
                      const float* __restrict__ asrc_in, const float* __restrict__ adst_in,
                      __half* __restrict__ hout16, float* __restrict__ houtf,
                      float* __restrict__ asrc_out, float* __restrict__ adst_out) {
    __shared__ float Ws[H * H];
    __shared__ float As[H], Ad[H];
    int t = threadIdx.x;
    if (FUSED) {
        for (int i = t; i < H * H; i += 256) Ws[i] = Wn[i];
        if (t < H) { As[t] = asn[t]; Ad[t] = adn[t]; }
        __syncthreads();
    }

    int lane = t & 31;
    int n = blockIdx.x * 8 + (t >> 5);
    float2 ce = d_ce[layer];
    int rs = d_rowptr[n], re = d_rowptr[n + 1];
    float ad = adst_in[n];
    int len = re - rs;
    int nch = (len + 31) >> 5;
    bool fast = (nch <= 4);
    const float4* ent4 = (const float4*)d_ent;

    float m = BIG_NEG, s = 0.f;
    int sv[4]; float lv[4];

    if (fast) {
        #pragma unroll
        for (int c = 0; c < 4; c++) { sv[c] = 0; lv[c] = BIG_NEG; }
        #pragma unroll
        for (int c = 0; c < 4; c++) {
            if (c < nch) {
                int e = rs + c * 32 + lane;
                if (e < re) {
                    float4 ev = ent4[e];
                    int srcn = __float_as_int(ev.x);
                    float l = asrc_in[srcn] + ad + ev.z * ce.x + ev.w * ce.y;
                    l = (l >= 0.f) ? l : 0.2f * l;
                    sv[c] = srcn; lv[c] = l;
                    if (l > m) { s = s * __expf(m - l) + 1.f; m = l; }
                    else       { s += __expf(l - m); }
                }
            }
        }
    } else {
        for (int b = rs; b < re; b += 32) {
            int e = b + lane;
            if (e < re) {
                float4 ev = ent4[e];
                int srcn = __float_as_int(ev.x);
                float l = asrc_in[srcn] + ad + ev.z * ce.x + ev.w * ce.y;
                l = (l >= 0.f) ? l : 0.2f * l;
                if (l > m) { s = s * __expf(m - l) + 1.f; m = l; }
                else       { s += __expf(l - m); }
            }
        }
    }

    #pragma unroll
    for (int off = 16; off; off >>= 1) {
        float mo = __shfl_xor_sync(~0u, m, off);
        float so = __shfl_xor_sync(~0u, s, off);
        float mn = fmaxf(m, mo);
        s = s * __expf(m - mn) + so * __expf(mo - mn);
        m = mn;
    }
    float inv_s = 1.f / s;

    float acc0 = 0.f, acc1 = 0.f;
    if (fast) {
        #pragma unroll
        for (int c = 0; c < 4; c++) {
            if (c < nch) {
                float w = __expf(lv[c] - m) * inv_s;
                int cnt = min(32, re - (rs + c * 32));
                if (cnt == 32) {
                    #pragma unroll
                    for (int j = 0; j < 32; j += 2) {
                        int   s0 = __shfl_sync(~0u, sv[c], j);
                        float w0 = __shfl_sync(~0u, w, j);
                        int   s1 = __shfl_sync(~0u, sv[c], j + 1);
                        float w1 = __shfl_sync(~0u, w, j + 1);
                        acc0 = fmaf(w0, __half2float(hlin[s0 * H + lane]), acc0);
                        acc1 = fmaf(w1, __half2float(hlin[s1 * H + lane]), acc1);
                    }
                } else {
                    #pragma unroll 4
                    for (int j = 0; j < cnt; j++) {
                        int   sj = __shfl_sync(~0u, sv[c], j);
                        float wj = __shfl_sync(~0u, w, j);
                        acc0 = fmaf(wj, __half2float(hlin[sj * H + lane]), acc0);
                    }
                }
            }
        }
    } else {
        for (int b = rs; b < re; b += 32) {
            int e = b + lane;
            float w = 0.f; int srcn = 0;
            if (e < re) {
                float4 ev = ent4[e];
                srcn = __float_as_int(ev.x);
                float l = asrc_in[srcn] + ad + ev.z * ce.x + ev.w * ce.y;
                l = (l >= 0.f) ? l : 0.2f * l;
                w = __expf(l - m) * inv_s;
            }
            int cnt = min(32, re - b);
            #pragma unroll 4
            for (int j = 0; j < cnt; j++) {
                int   sj = __shfl_sync(~0u, srcn, j);
                float wj = __shfl_sync(~0u, w, j);
                acc0 = fmaf(wj, __half2float(hlin[sj * H + lane]), acc0);
            }
        }
    }

    float o = acc0 + acc1 + bias[lane];
    if (FUSED) {
        o = fmaxf(o, 0.f);
        float hn = 0.f;
        #pragma unroll
        for (int k = 0; k < H; k++)
            hn = fmaf(__shfl_sync(~0u, o, k), Ws[k * H + lane], hn);
        hout16[n * H + lane] = __float2half(hn);
        float ps = hn * As[lane], pd = hn * Ad[lane];
        #pragma unroll
        for (int off = 16; off; off >>= 1) {
            ps += __shfl_xor_sync(~0u, ps, off);
            pd += __shfl_xor_sync(~0u, pd, off);
        }
        if (lane == 0) { asrc_out[n] = ps; adst_out[n] = pd; }
    } else {
        houtf[n * H + lane] = o;
    }
}

// ---------------- pool + linear + relu ----------------
__global__ void k_pool(const float* __restrict__ h, const float* __restrict__ lw,
                       const float* __restrict__ lb, float* __restrict__ out) {
    int lane = threadIdx.x & 31;
    int g = blockIdx.x * 8 + (threadIdx.x >> 5);
    if (g >= NG) return;
    const float* p = h + g * NPG * H;
    float acc = 0.f;
    #pragma unroll 6
    for (int r = 0; r < NPG; r++) acc += p[r * H + lane];
    float t = acc * lw[lane];
    #pragma unroll
    for (int off = 16; off; off >>= 1) t += __shfl_xor_sync(~0u, t, off);
    if (lane == 0) out[g] = fmaxf(t + lb[0], 0.f);
}

// ---------------- launch ----------------
extern "C" void kernel_launch(void* const* d_in, const int* in_sizes, int n_in,
                              void* d_out, int out_size) {
    const float*  x    = (const float*)d_in[0];
    const int*    ei   = (const int*)d_in[1];
    const float2* ea   = (const float2*)d_in[2];
    const float*  W0   = (const float*)d_in[3];
    const float*  Ws   = (const float*)d_in[4];
    const float*  as_  = (const float*)d_in[5];
    const float*  ad_  = (const float*)d_in[6];
    const float*  We   = (const float*)d_in[7];
    const float*  ae_  = (const float*)d_in[8];
    const float*  bias = (const float*)d_in[9];
    const float*  lw   = (const float*)d_in[10];
    const float*  lb   = (const float*)d_in[11];
    float* out = (float*)d_out;

    __half *hA, *hB; float *hF, *asA, *adA, *asB, *adB;
    cudaGetSymbolAddress((void**)&hA, d_h16A);
    cudaGetSymbolAddress((void**)&hB, d_h16B);
    cudaGetSymbolAddress((void**)&hF, d_hfin);
    cudaGetSymbolAddress((void**)&asA, d_asrcA);
    cudaGetSymbolAddress((void**)&adA, d_adstA);
    cudaGetSymbolAddress((void**)&asB, d_asrcB);
    cudaGetSymbolAddress((void**)&adB, d_adstB);

    k_init<<<(NN + 255) / 256, 256>>>();
    k_consts<<<1, 160>>>(W0, as_, ad_, We, ae_);
    k_hist<<<NE / 1024, 256>>>(ei);
    k_scanA<<<NBLK, 1024>>>();
    k_scanB<<<1, 32>>>();
    k_scanC<<<(NN + 255) / 256, 256>>>();
    k_scatter<<<NE / 1024, 256>>>(ei, ea);
    k_loop<<<NN / 8, 256>>>();

    k_layer0<<<NN / 8, 256>>>(x, W0);
    k_agg<1><<<NN / 8, 256>>>(hB, bias + 0 * H, 0, Ws + 0 * H * H, as_ + 1 * H, ad_ + 1 * H,
                              asA, adA, hA, nullptr, asB, adB);
    k_agg<1><<<NN / 8, 256>>>(hA, bias + 1 * H, 1, Ws + 1 * H * H, as_ + 2 * H, ad_ + 2 * H,
                              asB, adB, hB, nullptr, asA, adA);
    k_agg<1><<<NN / 8, 256>>>(hB, bias + 2 * H, 2, Ws + 2 * H * H, as_ + 3 * H, ad_ + 3 * H,
                              asA, adA, hA, nullptr, asB, adB);
    k_agg<0><<<NN / 8, 256>>>(hA, bias + 3 * H, 3, nullptr, nullptr, nullptr,
                              asB, adB, nullptr, hF, nullptr, nullptr);
    k_pool<<<128, 256>>>(hF, lw, lb, out);
}

// round 5
// speedup vs baseline: 2.1961x; 1.3720x over previous
#include <cuda_runtime.h>
#include <cuda_fp16.h>

#define NN 86016
#define NE 4194304
#define H 32
#define NG 1024
#define NPG 84
#define ETOT (NE + NN)
#define NBLK 84
#define BIG_NEG -1e30f

// 8B CSR entry
struct __align__(8) Ent { int src; __half2 ea; };

// ---------------- device scratch ----------------
__device__ int    d_deg[NN];
__device__ int    d_cur[NN];
__device__ int    d_rowptr[NN + 1];
__device__ int    d_rowloc[NN];
__device__ int    d_blksum[NBLK];
__device__ int    d_blkoff[NBLK];
__device__ Ent    d_ent[ETOT];
__device__ __half d_h16A[NN * H];
__device__ __half d_h16B[NN * H];
__device__ float  d_hfin[NN * H];
__device__ __half d_asA[NN], d_asB[NN];     // fp16 asrc (L1-resident gather)
__device__ float  d_adA[NN], d_adB[NN];     // fp32 adst (1 read/node)
__device__ float2 d_ce[4];
__device__ float  d_c0[2];

// ---------------- init ----------------
__global__ void k_init() {
    int i = blockIdx.x * blockDim.x + threadIdx.x;
    if (i < NN) d_deg[i] = 0;
}

__global__ void k_consts(const float* __restrict__ W0, const float* __restrict__ a_s,
                         const float* __restrict__ a_d, const float* __restrict__ We,
                         const float* __restrict__ a_e) {
    int w = threadIdx.x >> 5, lane = threadIdx.x & 31;
    if (w < 4) {
        float ae = a_e[w * 32 + lane];
        float p0 = We[w * 64 + lane] * ae;
        float p1 = We[w * 64 + 32 + lane] * ae;
        #pragma unroll
        for (int o = 16; o; o >>= 1) {
            p0 += __shfl_xor_sync(~0u, p0, o);
            p1 += __shfl_xor_sync(~0u, p1, o);
        }
        if (lane == 0) d_ce[w] = make_float2(p0, p1);
    } else {
        float w0 = W0[lane];
        float ps = w0 * a_s[lane];
        float pd = w0 * a_d[lane];
        #pragma unroll
        for (int o = 16; o; o >>= 1) {
            ps += __shfl_xor_sync(~0u, ps, o);
            pd += __shfl_xor_sync(~0u, pd, o);
        }
        if (lane == 0) { d_c0[0] = ps; d_c0[1] = pd; }
    }
}

// ---------------- CSR build ----------------
__global__ void k_hist(const int* __restrict__ ei) {
    int e4 = blockIdx.x * blockDim.x + threadIdx.x;
    int e = e4 * 4;
    if (e >= NE) return;
    int4 d = *(const int4*)(ei + NE + e);
    atomicAdd(&d_deg[d.x], 1);
    atomicAdd(&d_deg[d.y], 1);
    atomicAdd(&d_deg[d.z], 1);
    atomicAdd(&d_deg[d.w], 1);
}

__global__ void k_scanA() {
    __shared__ int sm[1024];
    int t = threadIdx.x;
    int n = blockIdx.x * 1024 + t;
    int sz = d_deg[n] + 1;
    sm[t] = sz;
    __syncthreads();
    #pragma unroll
    for (int off = 1; off < 1024; off <<= 1) {
        int v = (t >= off) ? sm[t - off] : 0;
        __syncthreads();
        sm[t] += v;
        __syncthreads();
    }
    d_rowloc[n] = sm[t] - sz;
    if (t == 1023) d_blksum[blockIdx.x] = sm[1023];
}

__global__ void k_scanB() {
    if (threadIdx.x == 0) {
        int acc = 0;
        #pragma unroll 4
        for (int b = 0; b < NBLK; b++) { d_blkoff[b] = acc; acc += d_blksum[b]; }
    }
}

__global__ void k_scanC() {
    int n = blockIdx.x * blockDim.x + threadIdx.x;
    if (n >= NN) return;
    int p = d_rowloc[n] + d_blkoff[n >> 10];
    d_rowptr[n] = p;
    if (n == 0) d_rowptr[NN] = ETOT;
    d_ent[p].src = n;          // self loop; ea filled by k_loop
    d_cur[n] = p + 1;
}

__global__ void k_scatter(const int* __restrict__ ei, const float2* __restrict__ ea) {
    int e4 = blockIdx.x * blockDim.x + threadIdx.x;
    int e = e4 * 4;
    if (e >= NE) return;
    int4 s = *(const int4*)(ei + e);
    int4 d = *(const int4*)(ei + NE + e);
    float4 a01 = *(const float4*)(ea + e);
    float4 a23 = *(const float4*)(ea + e + 2);
    int2* ent = (int2*)d_ent;
    __half2 h0 = __floats2half2_rn(a01.x, a01.y);
    __half2 h1 = __floats2half2_rn(a01.z, a01.w);
    __half2 h2 = __floats2half2_rn(a23.x, a23.y);
    __half2 h3 = __floats2half2_rn(a23.z, a23.w);
    int p;
    p = atomicAdd(&d_cur[d.x], 1); ent[p] = make_int2(s.x, *(int*)&h0);
    p = atomicAdd(&d_cur[d.y], 1); ent[p] = make_int2(s.y, *(int*)&h1);
    p = atomicAdd(&d_cur[d.z], 1); ent[p] = make_int2(s.z, *(int*)&h2);
    p = atomicAdd(&d_cur[d.w], 1); ent[p] = make_int2(s.w, *(int*)&h3);
}

// self-loop edge attr = mean of incoming edge attrs
__global__ void k_loop() {
    int lane = threadIdx.x & 31;
    int n = blockIdx.x * 8 + (threadIdx.x >> 5);
    int rs = d_rowptr[n], re = d_rowptr[n + 1];
    float sx = 0.f, sy = 0.f;
    for (int e = rs + 1 + lane; e < re; e += 32) {
        float2 a = __half22float2(d_ent[e].ea);
        sx += a.x; sy += a.y;
    }
    #pragma unroll
    for (int off = 16; off; off >>= 1) {
        sx += __shfl_xor_sync(~0u, sx, off);
        sy += __shfl_xor_sync(~0u, sy, off);
    }
    if (lane == 0) {
        int dg = re - rs - 1;
        float dd = (float)(dg > 0 ? dg : 1);
        d_ent[rs].ea = __floats2half2_rn(sx / dd, sy / dd);
    }
}

// ---------------- layer 0 node transform ----------------
__global__ void k_layer0(const float* __restrict__ x, const float* __restrict__ W0) {
    int lane = threadIdx.x & 31;
    int n = blockIdx.x * 8 + (threadIdx.x >> 5);
    float v = x[n];
    d_h16B[n * H + lane] = __float2half(v * W0[lane]);
    if (lane == 0) { d_asA[n] = __float2half(v * d_c0[0]); d_adA[n] = v * d_c0[1]; }
}

// ---------------- GAT agg (+ fused next-layer transform) ----------------
template<int FUSED>
__global__ void k_agg(const __half* __restrict__ hlin,
                      const float* __restrict__ bias, int layer,
                      const float* __restrict__ Wn, const float* __restrict__ asn,
                      const float* __restrict__ adn,
                      const __half* __restrict__ asrc_in, const float* __restrict__ adst_in,
                      __half* __restrict__ hout16, float* __restrict__ houtf,
                      __half* __restrict__ asrc_out, float* __restrict__ adst_out) {
    __shared__ float Ws[H * H];
    __shared__ float As[H], Ad[H];
    __shared__ uint2 smp[8][128];      // (w, src) per warp, 4 chunks x 32
    int t = threadIdx.x;
    if (FUSED) {
        for (int i = t; i < H * H; i += 256) Ws[i] = Wn[i];
        if (t < H) { As[t] = asn[t]; Ad[t] = adn[t]; }
        __syncthreads();
    }

    int lane = t & 31;
    int wid = t >> 5;
    int n = blockIdx.x * 8 + wid;
    float2 ce = d_ce[layer];
    int rs = d_rowptr[n], re = d_rowptr[n + 1];
    float adv = adst_in[n];
    int len = re - rs;
    int nch = (len + 31) >> 5;
    bool fast = (nch <= 4);
    const int2* ent2 = (const int2*)d_ent;
    const __half2* h2 = (const __half2*)hlin;

    float o;
    if (fast) {
        // ---- phase 1: logits + max only ----
        int sv[4]; float lv[4];
        #pragma unroll
        for (int c = 0; c < 4; c++) { sv[c] = 0; lv[c] = BIG_NEG; }
        float m = BIG_NEG;
        #pragma unroll
        for (int c = 0; c < 4; c++) {
            if (c < nch) {
                int e = rs + c * 32 + lane;
                if (e < re) {
                    int2 ev = ent2[e];
                    __half2 eah = *reinterpret_cast<__half2*>(&ev.y);
                    float2 eaf = __half22float2(eah);
                    float l = __half2float(asrc_in[ev.x]) + adv + eaf.x * ce.x + eaf.y * ce.y;
                    l = (l >= 0.f) ? l : 0.2f * l;
                    sv[c] = ev.x; lv[c] = l;
                    m = fmaxf(m, l);
                }
            }
        }
        #pragma unroll
        for (int off = 16; off; off >>= 1)
            m = fmaxf(m, __shfl_xor_sync(~0u, m, off));

        // ---- phase 1.5: one exp per edge, stash (w, src) in smem ----
        float ssum = 0.f;
        #pragma unroll
        for (int c = 0; c < 4; c++) {
            if (c < nch) {
                float w = __expf(lv[c] - m);   // invalid lanes -> 0
                ssum += w;
                smp[wid][c * 32 + lane] = make_uint2(__float_as_uint(w), (unsigned)sv[c]);
            }
        }
        __syncwarp();
        #pragma unroll
        for (int off = 16; off; off >>= 1)
            ssum += __shfl_xor_sync(~0u, ssum, off);
        float inv_s = 1.f / ssum;

        // ---- phase 2: unnormalized weighted gather, half2 rows ----
        float2 acc = make_float2(0.f, 0.f);
        int half16 = lane >> 4;
        int fo = lane & 15;
        #pragma unroll
        for (int c = 0; c < 4; c++) {
            if (c < nch) {
                int cnt = min(32, len - c * 32);
                const uint2* pp = &smp[wid][c * 32];
                #pragma unroll 8
                for (int p = 0; p < cnt; p += 2) {
                    uint2 pr = pp[p + half16];
                    float w = __uint_as_float(pr.x);
                    float2 v = __half22float2(h2[(int)pr.y * 16 + fo]);
                    acc.x = fmaf(w, v.x, acc.x);
                    acc.y = fmaf(w, v.y, acc.y);
                }
            }
        }
        acc.x += __shfl_xor_sync(~0u, acc.x, 16);
        acc.y += __shfl_xor_sync(~0u, acc.y, 16);
        float ox = __shfl_sync(~0u, acc.x, lane >> 1);
        float oy = __shfl_sync(~0u, acc.y, lane >> 1);
        o = ((lane & 1) ? oy : ox) * inv_s + bias[lane];
    } else {
        // ---- streaming fallback (rows > 128 edges) ----
        float m = BIG_NEG, s = 0.f;
        for (int b = rs; b < re; b += 32) {
            int e = b + lane;
            if (e < re) {
                int2 ev = ent2[e];
                __half2 eah = *reinterpret_cast<__half2*>(&ev.y);
                float2 eaf = __half22float2(eah);
                float l = __half2float(asrc_in[ev.x]) + adv + eaf.x * ce.x + eaf.y * ce.y;
                l = (l >= 0.f) ? l : 0.2f * l;
                if (l > m) { s = s * __expf(m - l) + 1.f; m = l; }
                else       { s += __expf(l - m); }
            }
        }
        #pragma unroll
        for (int off = 16; off; off >>= 1) {
            float mo = __shfl_xor_sync(~0u, m, off);
            float so = __shfl_xor_sync(~0u, s, off);
            float mn = fmaxf(m, mo);
            s = s * __expf(m - mn) + so * __expf(mo - mn);
            m = mn;
        }
        float inv_s = 1.f / s;
        float acc = 0.f;
        for (int b = rs; b < re; b += 32) {
            int e = b + lane;
            float w = 0.f; int srcn = 0;
            if (e < re) {
                int2 ev = ent2[e];
                __half2 eah = *reinterpret_cast<__half2*>(&ev.y);
                float2 eaf = __half22float2(eah);
                float l = __half2float(asrc_in[ev.x]) + adv + eaf.x * ce.x + eaf.y * ce.y;
                l = (l >= 0.f) ? l : 0.2f * l;
                w = __expf(l - m) * inv_s;
                srcn = ev.x;
            }
            int cnt = min(32, re - b);
            #pragma unroll 4
            for (int j = 0; j < cnt; j++) {
                int   sj = __shfl_sync(~0u, srcn, j);
                float wj = __shfl_sync(~0u, w, j);
                acc = fmaf(wj, __half2float(hlin[sj * H + lane]), acc);
            }
        }
        o = acc + bias[lane];
    }

    if (FUSED) {
        o = fmaxf(o, 0.f);
        float hn = 0.f;
        #pragma unroll
        for (int k = 0; k < H; k++)
            hn = fmaf(__shfl_sync(~0u, o, k), Ws[k * H + lane], hn);
        hout16[n * H + lane] = __float2half(hn);
        float ps = hn * As[lane], pd = hn * Ad[lane];
        #pragma unroll
        for (int off = 16; off; off >>= 1) {
            ps += __shfl_xor_sync(~0u, ps, off);
            pd += __shfl_xor_sync(~0u, pd, off);
        }
        if (lane == 0) { asrc_out[n] = __float2half(ps); adst_out[n] = pd; }
    } else {
        houtf[n * H + lane] = o;
    }
}

// ---------------- pool + linear + relu ----------------
__global__ void k_pool(const float* __restrict__ h, const float* __restrict__ lw,
                       const float* __restrict__ lb, float* __restrict__ out) {
    int lane = threadIdx.x & 31;
    int g = blockIdx.x * 8 + (threadIdx.x >> 5);
    if (g >= NG) return;
    const float* p = h + g * NPG * H;
    float acc = 0.f;
    #pragma unroll 6
    for (int r = 0; r < NPG; r++) acc += p[r * H + lane];
    float t = acc * lw[lane];
    #pragma unroll
    for (int off = 16; off; off >>= 1) t += __shfl_xor_sync(~0u, t, off);
    if (lane == 0) out[g] = fmaxf(t + lb[0], 0.f);
}

// ---------------- launch ----------------
extern "C" void kernel_launch(void* const* d_in, const int* in_sizes, int n_in,
                              void* d_out, int out_size) {
    const float*  x    = (const float*)d_in[0];
    const int*    ei   = (const int*)d_in[1];
    const float2* ea   = (const float2*)d_in[2];
    const float*  W0   = (const float*)d_in[3];
    const float*  Ws   = (const float*)d_in[4];
    const float*  as_  = (const float*)d_in[5];
    const float*  ad_  = (const float*)d_in[6];
    const float*  We   = (const float*)d_in[7];
    const float*  ae_  = (const float*)d_in[8];
    const float*  bias = (const float*)d_in[9];
    const float*  lw   = (const float*)d_in[10];
    const float*  lb   = (const float*)d_in[11];
    float* out = (float*)d_out;

    __half *hA, *hB, *asA, *asB; float *hF, *adA, *adB;
    cudaGetSymbolAddress((void**)&hA, d_h16A);
    cudaGetSymbolAddress((void**)&hB, d_h16B);
    cudaGetSymbolAddress((void**)&hF, d_hfin);
    cudaGetSymbolAddress((void**)&asA, d_asA);
    cudaGetSymbolAddress((void**)&asB, d_asB);
    cudaGetSymbolAddress((void**)&adA, d_adA);
    cudaGetSymbolAddress((void**)&adB, d_adB);

    k_init<<<(NN + 255) / 256, 256>>>();
    k_consts<<<1, 160>>>(W0, as_, ad_, We, ae_);
    k_hist<<<NE / 1024, 256>>>(ei);
    k_scanA<<<NBLK, 1024>>>();
    k_scanB<<<1, 32>>>();
    k_scanC<<<(NN + 255) / 256, 256>>>();
    k_scatter<<<NE / 1024, 256>>>(ei, ea);
    k_loop<<<NN / 8, 256>>>();

    k_layer0<<<NN / 8, 256>>>(x, W0);
    k_agg<1><<<NN / 8, 256>>>(hB, bias + 0 * H, 0, Ws + 0 * H * H, as_ + 1 * H, ad_ + 1 * H,
                              asA, adA, hA, nullptr, asB, adB);
    k_agg<1><<<NN / 8, 256>>>(hA, bias + 1 * H, 1, Ws + 1 * H * H, as_ + 2 * H, ad_ + 2 * H,
                              asB, adB, hB, nullptr, asA, adA);
    k_agg<1><<<NN / 8, 256>>>(hB, bias + 2 * H, 2, Ws + 2 * H * H, as_ + 3 * H, ad_ + 3 * H,
                              asA, adA, hA, nullptr, asB, adB);
    k_agg<0><<<NN / 8, 256>>>(hA, bias + 3 * H, 3, nullptr, nullptr, nullptr,
                              asB, adB, nullptr, hF, nullptr, nullptr);
    k_pool<<<128, 256>>>(hF, lw, lb, out);
}